// round 3
// baseline (speedup 1.0000x reference)
#include <cuda_runtime.h>
#include <math.h>

// Problem constants: N=20000, E=640000, S=128, V=16, E_DIM=32
#define MAXN 20000

__device__ float g_agg_s[MAXN * 128];
__device__ float g_agg_v[MAXN * 48];

typedef unsigned long long ull;

__device__ __forceinline__ float sigmoidf_(float x) {
    return 1.0f / (1.0f + __expf(-x));
}
// packed f32x2 helpers (Blackwell FFMA2 path)
__device__ __forceinline__ ull pk2(float x) {
    ull r; asm("mov.b64 %0, {%1, %1};" : "=l"(r) : "f"(x)); return r;
}
__device__ __forceinline__ void fma2_(ull& d, ull a, ull b) {
    asm("fma.rn.f32x2 %0, %1, %2, %0;" : "+l"(d) : "l"(a), "l"(b));
}
__device__ __forceinline__ float2 up2(ull p) {
    float2 r; asm("mov.b64 {%0, %1}, %2;" : "=f"(r.x), "=f"(r.y) : "l"(p)); return r;
}

// ---------------------------------------------------------------------------
__global__ void zero_kernel(int n) {
    int total = n * 176;
    for (int i = blockIdx.x * blockDim.x + threadIdx.x; i < total;
         i += gridDim.x * blockDim.x) {
        if (i < n * 128) g_agg_s[i] = 0.0f;
        else             g_agg_v[i - n * 128] = 0.0f;
    }
}

// ---------------------------------------------------------------------------
// Edge kernel: 64 edges/CTA, 256 threads, FFMA2 GEMMs.
// Shared layout (float offsets):
//   sxT  [336][68]  @ 0       (22848)   K-major X, stride 68
//   swt  [2][16][128] @ 22848 (4096)    double-buffered W tile
//   sv   [64][100]  @ 26944   (6400)    v inputs (33 x 3 per edge)
//   sg   [64][16]   @ 33344   (1024)
//   sWv  [33][16]   @ 34368   (528)
//   idx  128 ints   @ 34896   (128)
// aliases (inside sxT, dead after GEMM1/GEMM2 resp.):
//   stt  [64][132] @ 0     (8448)   silu(h), edge-major
//   sms  [64][132] @ 8448  (8448)   m_s
//   sWgT [16][128] @ 22848 (2048)   aliases swt (dead after GEMM2)
#define BE 64
#define ET 256
#define OFF_SWT 22848
#define OFF_SV  26944
#define OFF_SG  33344
#define OFF_SWV 34368
#define OFF_IDX 34896
#define EDGE_SMEM_BYTES (35024 * 4)

__global__ __launch_bounds__(256) void edge_kernel(
    const float* __restrict__ s, const float* __restrict__ v,
    const int* __restrict__ ei, const float* __restrict__ es,
    const float* __restrict__ ev,
    const float* __restrict__ W1, const float* __restrict__ b1,
    const float* __restrict__ W2, const float* __restrict__ b2,
    const float* __restrict__ Wv, const float* __restrict__ Wg,
    const float* __restrict__ bg, int E)
{
    extern __shared__ __align__(16) float sm[];
    float* sxT  = sm;
    float* swt  = sm + OFF_SWT;
    float* sv   = sm + OFF_SV;
    float* sg   = sm + OFF_SG;
    float* sWv  = sm + OFF_SWV;
    int*   ssrc = (int*)(sm + OFF_IDX);
    int*   sdst = ssrc + BE;
    float* stt  = sm;             // alias
    float* sms  = sm + 8448;      // alias
    float* sWgT = sm + OFF_SWT;   // alias

    const int tid = threadIdx.x;
    const int e0  = blockIdx.x * BE;
    const int nval = min(BE, E - e0);

    if (tid < BE) {
        int ee = e0 + min(tid, nval - 1);
        ssrc[tid] = ei[ee];
        sdst[tid] = ei[E + ee];
    }
    __syncthreads();

    // ---- gather scalar features into K-major X ----
    for (int idx = tid; idx < BE * 288; idx += ET) {
        int e = idx / 288;
        int k = idx - e * 288;
        int eg = e0 + (e < nval ? e : 0);
        float val;
        if (k < 128)      val = s[ssrc[e] * 128 + k];
        else if (k < 256) val = s[sdst[e] * 128 + (k - 128)];
        else              val = es[eg * 32 + (k - 256)];
        sxT[k * 68 + e] = val;
    }
    // ---- gather vector features ----
    for (int idx = tid; idx < BE * 99; idx += ET) {
        int e = idx / 99;
        int j = idx - e * 99;
        int eg = e0 + (e < nval ? e : 0);
        float val;
        if (j < 48)      val = v[ssrc[e] * 48 + j];
        else if (j < 96) val = v[sdst[e] * 48 + (j - 48)];
        else             val = ev[eg * 3 + (j - 96)];
        sv[e * 100 + j] = val;
    }
    // zero-pad K rows 322..335
    for (int idx = tid; idx < 14 * BE; idx += ET) {
        sxT[(322 + idx / BE) * 68 + (idx % BE)] = 0.0f;
    }
    __syncthreads();
    // ---- vector norms -> X rows 288..321 ----
    for (int idx = tid; idx < BE * 33; idx += ET) {
        int e = idx / 33;
        int j = idx - e * 33;
        float a = sv[e * 100 + j * 3 + 0];
        float b = sv[e * 100 + j * 3 + 1];
        float c = sv[e * 100 + j * 3 + 2];
        float nn = sqrtf(fmaxf(a * a + b * b + c * c, 1e-8f));
        sxT[(289 + j) * 68 + e] = nn;
        if (j == 32) sxT[288 * 68 + e] = nn;  // edge_len == |edge_v|
    }

    const int tx = tid & 15;   // 8 cols: 8*tx .. 8*tx+7
    const int ty = tid >> 4;   // 4 edges: 4*ty .. 4*ty+3

    ull acc[4][4];
#pragma unroll
    for (int i = 0; i < 4; ++i)
#pragma unroll
        for (int j = 0; j < 4; ++j) acc[i][j] = 0ull;

    // ---- GEMM1: K = 336 (21 tiles of 16), FFMA2 ----
    const float4* W14 = (const float4*)W1;
    {   // prefetch tile 0 (note: barrier below also covers gather/norm writes)
        float4* dst = (float4*)swt;
        for (int i = tid; i < 512; i += ET) {
            int k = i >> 5;
            dst[i] = (k < 322) ? W14[k * 32 + (i & 31)]
                               : make_float4(0.f, 0.f, 0.f, 0.f);
        }
    }
    __syncthreads();
    for (int kt = 0; kt < 21; ++kt) {
        if (kt + 1 < 21) {
            float4* dst = (float4*)(swt + ((kt + 1) & 1) * 2048);
            for (int i = tid; i < 512; i += ET) {
                int k = (kt + 1) * 16 + (i >> 5);
                dst[i] = (k < 322) ? W14[k * 32 + (i & 31)]
                                   : make_float4(0.f, 0.f, 0.f, 0.f);
            }
        }
        const float* wb = swt + (kt & 1) * 2048;
#pragma unroll 4
        for (int kk = 0; kk < 16; ++kk) {
            float4 xv = *(const float4*)&sxT[(kt * 16 + kk) * 68 + 4 * ty];
            const ulonglong2* wr = (const ulonglong2*)&wb[kk * 128 + 8 * tx];
            ulonglong2 wA = wr[0], wB = wr[1];
            ull xp[4] = {pk2(xv.x), pk2(xv.y), pk2(xv.z), pk2(xv.w)};
#pragma unroll
            for (int i = 0; i < 4; ++i) {
                fma2_(acc[i][0], xp[i], wA.x);
                fma2_(acc[i][1], xp[i], wA.y);
                fma2_(acc[i][2], xp[i], wB.x);
                fma2_(acc[i][3], xp[i], wB.y);
            }
        }
        __syncthreads();
    }

    // ---- epilogue 1: bias + silu -> stt (edge-major), then W2 tile0 ----
    {
        const float4* b14 = (const float4*)b1;
        float4 bA = b14[2 * tx], bB = b14[2 * tx + 1];
#pragma unroll
        for (int i = 0; i < 4; ++i) {
            float2 p0 = up2(acc[i][0]), p1 = up2(acc[i][1]);
            float2 p2 = up2(acc[i][2]), p3 = up2(acc[i][3]);
            float h[8] = {p0.x + bA.x, p0.y + bA.y, p1.x + bA.z, p1.y + bA.w,
                          p2.x + bB.x, p2.y + bB.y, p3.x + bB.z, p3.y + bB.w};
            float t[8];
#pragma unroll
            for (int j = 0; j < 8; ++j) t[j] = h[j] * sigmoidf_(h[j]);
            float* dst = &stt[(4 * ty + i) * 132 + 8 * tx];
            *(float4*)dst       = make_float4(t[0], t[1], t[2], t[3]);
            *(float4*)(dst + 4) = make_float4(t[4], t[5], t[6], t[7]);
        }
    }
    const float4* W24 = (const float4*)W2;
    {
        float4* dst = (float4*)swt;
        for (int i = tid; i < 512; i += ET)
            dst[i] = W24[(i >> 5) * 32 + (i & 31)];
    }
    __syncthreads();

    // ---- GEMM2: K = 128 (8 tiles of 16), FFMA2 ----
#pragma unroll
    for (int i = 0; i < 4; ++i)
#pragma unroll
        for (int j = 0; j < 4; ++j) acc[i][j] = 0ull;

    for (int kt = 0; kt < 8; ++kt) {
        if (kt + 1 < 8) {
            float4* dst = (float4*)(swt + ((kt + 1) & 1) * 2048);
            for (int i = tid; i < 512; i += ET) {
                int k = (kt + 1) * 16 + (i >> 5);
                dst[i] = W24[k * 32 + (i & 31)];
            }
        }
        const float* wb = swt + (kt & 1) * 2048;
#pragma unroll 4
        for (int kk = 0; kk < 16; ++kk) {
            int k = kt * 16 + kk;
            const ulonglong2* wr = (const ulonglong2*)&wb[kk * 128 + 8 * tx];
            ulonglong2 wA = wr[0], wB = wr[1];
            ull xp[4];
#pragma unroll
            for (int i = 0; i < 4; ++i)
                xp[i] = pk2(stt[(4 * ty + i) * 132 + k]);
#pragma unroll
            for (int i = 0; i < 4; ++i) {
                fma2_(acc[i][0], xp[i], wA.x);
                fma2_(acc[i][1], xp[i], wA.y);
                fma2_(acc[i][2], xp[i], wB.x);
                fma2_(acc[i][3], xp[i], wB.y);
            }
        }
        __syncthreads();
    }

    // ---- epilogue 2: bias -> sms, scatter-add m_s ----
    {
        const float4* b24 = (const float4*)b2;
        float4 bA = b24[2 * tx], bB = b24[2 * tx + 1];
#pragma unroll
        for (int i = 0; i < 4; ++i) {
            int e = 4 * ty + i;
            float2 p0 = up2(acc[i][0]), p1 = up2(acc[i][1]);
            float2 p2 = up2(acc[i][2]), p3 = up2(acc[i][3]);
            float m[8] = {p0.x + bA.x, p0.y + bA.y, p1.x + bA.z, p1.y + bA.w,
                          p2.x + bB.x, p2.y + bB.y, p3.x + bB.z, p3.y + bB.w};
            float* dst = &sms[e * 132 + 8 * tx];
            *(float4*)dst       = make_float4(m[0], m[1], m[2], m[3]);
            *(float4*)(dst + 4) = make_float4(m[4], m[5], m[6], m[7]);
            if (e < nval) {
                float* ga = &g_agg_s[sdst[e] * 128 + 8 * tx];
#pragma unroll
                for (int j = 0; j < 8; ++j) atomicAdd(ga + j, m[j]);
            }
        }
    }
    // stage Wg^T and Wv into smem (swt dead now)
    for (int i = tid; i < 2048; i += ET) {
        int w = i >> 7, c = i & 127;
        sWgT[i] = Wg[c * 16 + w];
    }
    for (int i = tid; i < 528; i += ET) sWv[i] = Wv[i];
    __syncthreads();

    // ---- gates: sigmoid(ms @ Wg + bg), FFMA2 ----
    for (int q = tid; q < BE * 16; q += ET) {
        int e = q >> 4, w = q & 15;
        ull g2 = 0ull;
        const ull* msp = (const ull*)&sms[e * 132];
        const ull* wgp = (const ull*)&sWgT[w * 128];
#pragma unroll 8
        for (int c = 0; c < 64; ++c) fma2_(g2, msp[c], wgp[c]);
        float2 gf = up2(g2);
        sg[e * 16 + w] = sigmoidf_(gf.x + gf.y + bg[w]);
    }
    __syncthreads();

    // ---- v projection * gate, scatter-add ----
    for (int q = tid; q < BE * 48; q += ET) {
        int e  = q / 48;
        int r  = q - e * 48;
        int w  = r / 3;
        int cc = r - w * 3;
        float a = 0.0f;
#pragma unroll
        for (int j = 0; j < 33; ++j)
            a = fmaf(sv[e * 100 + j * 3 + cc], sWv[j * 16 + w], a);
        a *= sg[e * 16 + w];
        if (e < nval) atomicAdd(&g_agg_v[sdst[e] * 48 + r], a);
    }
}

// ---------------------------------------------------------------------------
// Node update kernel (unchanged from working r1 kernel)
// ---------------------------------------------------------------------------
__global__ __launch_bounds__(128) void node_kernel(
    const float* __restrict__ s, const float* __restrict__ v,
    const float* __restrict__ W1, const float* __restrict__ b1,
    const float* __restrict__ W2, const float* __restrict__ b2,
    const float* __restrict__ Wv, const float* __restrict__ Wg,
    const float* __restrict__ bg, const float* __restrict__ lng,
    const float* __restrict__ lnb,
    float* __restrict__ out_s, float* __restrict__ out_v, int n)
{
    __shared__ float xu[8][292];
    __shared__ float vin[8][96];
    __shared__ float tt[8][128];
    __shared__ float dsm[8][132];
    __shared__ float gate[8][16];
    __shared__ float rsum[8][4], rsq[8][4];

    const int tid = threadIdx.x;
    const int n0 = blockIdx.x * 8;

    for (int idx = tid; idx < 8 * 256; idx += 128) {
        int i = idx >> 8, k = idx & 255;
        int nd = min(n0 + i, n - 1);
        xu[i][k] = (k < 128) ? s[nd * 128 + k] : g_agg_s[nd * 128 + (k - 128)];
    }
    for (int idx = tid; idx < 8 * 96; idx += 128) {
        int i = idx / 96, k = idx - i * 96;
        int nd = min(n0 + i, n - 1);
        vin[i][k] = (k < 48) ? v[nd * 48 + k] : g_agg_v[nd * 48 + (k - 48)];
    }
    __syncthreads();
    for (int idx = tid; idx < 8 * 32; idx += 128) {
        int i = idx >> 5, j = idx & 31;
        float a = vin[i][j * 3], b = vin[i][j * 3 + 1], c = vin[i][j * 3 + 2];
        xu[i][256 + j] = sqrtf(fmaxf(a * a + b * b + c * c, 1e-8f));
    }
    __syncthreads();

    const int c = tid;
    float acc[8];
    {
        float bb = b1[c];
#pragma unroll
        for (int i = 0; i < 8; ++i) acc[i] = bb;
    }
    for (int k = 0; k < 288; ++k) {
        float w = W1[k * 128 + c];
#pragma unroll
        for (int i = 0; i < 8; ++i) acc[i] = fmaf(xu[i][k], w, acc[i]);
    }
#pragma unroll
    for (int i = 0; i < 8; ++i) {
        float h = acc[i];
        tt[i][c] = h * sigmoidf_(h);
    }
    __syncthreads();

    float acc2[8];
    {
        float bb = b2[c];
#pragma unroll
        for (int i = 0; i < 8; ++i) acc2[i] = bb;
    }
    for (int k = 0; k < 128; ++k) {
        float w = W2[k * 128 + c];
#pragma unroll
        for (int i = 0; i < 8; ++i) acc2[i] = fmaf(tt[i][k], w, acc2[i]);
    }
#pragma unroll
    for (int i = 0; i < 8; ++i) dsm[i][c] = acc2[i];
    __syncthreads();

    {
        int i = tid >> 4, w = tid & 15;
        float g = bg[w];
        for (int cc = 0; cc < 128; ++cc)
            g = fmaf(dsm[i][cc], Wg[cc * 16 + w], g);
        gate[i][w] = sigmoidf_(g);
    }

    float val[8];
#pragma unroll
    for (int i = 0; i < 8; ++i) {
        int nd = min(n0 + i, n - 1);
        val[i] = s[nd * 128 + c] + acc2[i];
    }
    const int lane = tid & 31, wq = tid >> 5;
    float psum[8], psq[8];
#pragma unroll
    for (int i = 0; i < 8; ++i) { psum[i] = val[i]; psq[i] = val[i] * val[i]; }
#pragma unroll
    for (int off = 16; off > 0; off >>= 1) {
#pragma unroll
        for (int i = 0; i < 8; ++i) {
            psum[i] += __shfl_xor_sync(0xffffffffu, psum[i], off);
            psq[i]  += __shfl_xor_sync(0xffffffffu, psq[i],  off);
        }
    }
    if (lane == 0) {
#pragma unroll
        for (int i = 0; i < 8; ++i) { rsum[i][wq] = psum[i]; rsq[i][wq] = psq[i]; }
    }
    __syncthreads();

#pragma unroll
    for (int i = 0; i < 8; ++i) {
        if (n0 + i >= n) continue;
        float sum = rsum[i][0] + rsum[i][1] + rsum[i][2] + rsum[i][3];
        float sq  = rsq[i][0] + rsq[i][1] + rsq[i][2] + rsq[i][3];
        float mu  = sum * (1.0f / 128.0f);
        float var = sq * (1.0f / 128.0f) - mu * mu;
        float o = (val[i] - mu) * rsqrtf(var + 1e-5f) * lng[c] + lnb[c];
        out_s[(n0 + i) * 128 + c] = o;
    }

    for (int q = tid; q < 8 * 48; q += 128) {
        int i = q / 48, r = q - i * 48;
        if (n0 + i >= n) continue;
        int w = r / 3, cc = r - w * 3;
        float a = 0.0f;
#pragma unroll
        for (int j = 0; j < 32; ++j)
            a = fmaf(vin[i][j * 3 + cc], Wv[j * 16 + w], a);
        a *= gate[i][w];
        out_v[(n0 + i) * 48 + r] = v[(n0 + i) * 48 + r] + a;
    }
}

// ---------------------------------------------------------------------------
extern "C" void kernel_launch(void* const* d_in, const int* in_sizes, int n_in,
                              void* d_out, int out_size)
{
    const float* s   = (const float*)d_in[0];
    const float* v   = (const float*)d_in[1];
    const int*   ei  = (const int*)  d_in[2];
    const float* es  = (const float*)d_in[3];
    const float* ev  = (const float*)d_in[4];
    const float* mW1 = (const float*)d_in[5];
    const float* mb1 = (const float*)d_in[6];
    const float* mW2 = (const float*)d_in[7];
    const float* mb2 = (const float*)d_in[8];
    const float* mWv = (const float*)d_in[9];
    const float* mWg = (const float*)d_in[10];
    const float* mbg = (const float*)d_in[11];
    const float* uW1 = (const float*)d_in[12];
    const float* ub1 = (const float*)d_in[13];
    const float* uW2 = (const float*)d_in[14];
    const float* ub2 = (const float*)d_in[15];
    const float* uWv = (const float*)d_in[16];
    const float* uWg = (const float*)d_in[17];
    const float* ubg = (const float*)d_in[18];
    const float* lng = (const float*)d_in[19];
    const float* lnb = (const float*)d_in[20];

    const int n = in_sizes[0] / 128;
    const int E = in_sizes[2] / 2;

    float* out_s = (float*)d_out;
    float* out_v = out_s + (size_t)n * 128;

    cudaFuncSetAttribute(edge_kernel,
                         cudaFuncAttributeMaxDynamicSharedMemorySize,
                         EDGE_SMEM_BYTES);

    zero_kernel<<<(n * 176 + 255) / 256, 256>>>(n);

    edge_kernel<<<(E + BE - 1) / BE, ET, EDGE_SMEM_BYTES>>>(
        s, v, ei, es, ev, mW1, mb1, mW2, mb2, mWv, mWg, mbg, E);

    node_kernel<<<(n + 7) / 8, 128>>>(
        s, v, uW1, ub1, uW2, ub2, uWv, uWg, ubg, lng, lnb,
        out_s, out_v, n);
}